// round 9
// baseline (speedup 1.0000x reference)
#include <cuda_runtime.h>

#define LBL 32
#define BMAX 8
#define THR 256
#define NCHUNK 111       // chunks per batch -> grid = 8*111 = 888 = 148 SMs x 6
#define NGMAX 135424     // 736*736/4
typedef unsigned long long ull;
typedef long long ll;

#define S_EMB 65536.f
#define INV_S_EMB (1.f/65536.f)
#define S_VAL 262144.f
#define INV_S_VAL (1.f/262144.f)
#define S_LOC 512.f      // 2^9 local fixed-point scale (21-bit fields)

// global scratch (zeroed at module load; finalize re-zeros for next graph replay)
__device__ ull g_s01[BMAX * LBL];   // packed 32.32 (sum_e0, sum_e1)
__device__ ull g_s23[BMAX * LBL];   // packed 32.32 (sum_e2, sum_e3)
__device__ int g_cnt1[BMAX * LBL];  // kernel-region counts
__device__ ull g_p2[BMAX * LBL];    // packed (sum_val<<22) + cnt
__device__ unsigned g_bar1, g_bar2;
__device__ unsigned g_lab[BMAX * NGMAX];  // pass1->pass2 cached mask-labels (4x u8)

__device__ __forceinline__ void unpack2_32(ull p, float& a, float& b) {
    ll P = (ll)p;
    int ia = (int)(unsigned)(P & 0xFFFFFFFFll);
    int ib = (int)((P - (ll)ia) >> 32);
    a = (float)ia * INV_S_EMB;
    b = (float)ib * INV_S_EMB;
}
// 3x21-bit signed fields; exact borrow recovery (|field| < 2^20)
__device__ __forceinline__ ull pack3(float a, float b, float c) {
    return (ull)((ll)__float2int_rn(a * S_LOC)
               + ((ll)__float2int_rn(b * S_LOC) << 21)
               + ((ll)__float2int_rn(c * S_LOC) << 42));
}
__device__ __forceinline__ ull packB(float e3) {
    return (ull)((ll)__float2int_rn(e3 * S_LOC) + (1ll << 21));
}
__device__ __forceinline__ void unpack3(ull p, int& x, int& y, int& z) {
    ll P = (ll)p;
    x = (int)((P << 43) >> 43); P = (P - (ll)x) >> 21;
    y = (int)((P << 43) >> 43); P = (P - (ll)y) >> 21;
    z = (int)P;
}

__global__ void __launch_bounds__(THR, 6) k_fused(
    const float* __restrict__ emb, const int* __restrict__ inst,
    const float* __restrict__ ker, const float* __restrict__ tmk,
    float* __restrict__ out, int NG, int NPIX, int B)
{
    const int tid   = threadIdx.x;
    const int b     = blockIdx.x % B;
    const int chunk = blockIdx.x / B;
    const int CS    = (NG + NCHUNK - 1) / NCHUNK;
    const int gBeg  = chunk * CS;
    const int gEnd  = (gBeg + CS < NG) ? gBeg + CS : NG;

    __shared__ ull sA[LBL], sB[LBL], sp2[LBL];
    __shared__ float4 meanv[LBL];
    __shared__ int isLast;

    if (tid < LBL) { sA[tid] = 0ull; sB[tid] = 0ull; sp2[tid] = 0ull; }
    __syncthreads();

    const int4*   ip  = (const int4*)  (inst + (size_t)b * NPIX);
    const float4* kp  = (const float4*)(ker  + (size_t)b * NPIX);
    const float4* mp  = (const float4*)(tmk  + (size_t)b * NPIX);
    const float*  ep  = emb + (size_t)b * 4 * NPIX;
    const float4* e0p = (const float4*)(ep);
    const float4* e1p = (const float4*)(ep + NPIX);
    const float4* e2p = (const float4*)(ep + 2 * NPIX);
    const float4* e3p = (const float4*)(ep + 3 * NPIX);
    unsigned* glab = g_lab + (size_t)b * NGMAX;

    // ---------------- pass 1: kernel sums + label cache for pass 2 ------------
    // masks are read-once -> __ldcs (evict-first) so emb survives in L2 for pass 2
    for (int g = gBeg + 2 * tid; g < gEnd; g += 2 * THR) {
        const bool has2 = (g + 1 < gEnd);
        int4   lbA = __ldcs(ip + g);
        float4 kvA = __ldcs(kp + g);
        float4 mvA = __ldcs(mp + g);
        int4 lbB; float4 kvB, mvB;
        if (has2) { lbB = __ldcs(ip + g + 1); kvB = __ldcs(kp + g + 1); mvB = __ldcs(mp + g + 1); }

        int lm0 = (mvA.x > 0.5f) ? lbA.x : 0;
        int lm1 = (mvA.y > 0.5f) ? lbA.y : 0;
        int lm2 = (mvA.z > 0.5f) ? lbA.z : 0;
        int lm3 = (mvA.w > 0.5f) ? lbA.w : 0;
        glab[g] = (unsigned)lm0 | ((unsigned)lm1 << 8) | ((unsigned)lm2 << 16) | ((unsigned)lm3 << 24);
        int l0 = (kvA.x > 0.5f) ? lm0 : 0;
        int l1 = (kvA.y > 0.5f) ? lm1 : 0;
        int l2 = (kvA.z > 0.5f) ? lm2 : 0;
        int l3 = (kvA.w > 0.5f) ? lm3 : 0;

        int l4 = 0, l5 = 0, l6 = 0, l7 = 0;
        if (has2) {
            int lm4 = (mvB.x > 0.5f) ? lbB.x : 0;
            int lm5 = (mvB.y > 0.5f) ? lbB.y : 0;
            int lm6 = (mvB.z > 0.5f) ? lbB.z : 0;
            int lm7 = (mvB.w > 0.5f) ? lbB.w : 0;
            glab[g + 1] = (unsigned)lm4 | ((unsigned)lm5 << 8) | ((unsigned)lm6 << 16) | ((unsigned)lm7 << 24);
            l4 = (kvB.x > 0.5f) ? lm4 : 0;
            l5 = (kvB.y > 0.5f) ? lm5 : 0;
            l6 = (kvB.z > 0.5f) ? lm6 : 0;
            l7 = (kvB.w > 0.5f) ? lm7 : 0;
        }

        float4 e0A, e1A, e2A, e3A, e0B, e1B, e2B, e3B;
        const bool anyA = (l0 | l1 | l2 | l3) != 0;
        const bool anyB = (l4 | l5 | l6 | l7) != 0;
        if (anyA) { e0A = e0p[g]; e1A = e1p[g]; e2A = e2p[g]; e3A = e3p[g]; }
        if (anyB) { e0B = e0p[g+1]; e1B = e1p[g+1]; e2B = e2p[g+1]; e3B = e3p[g+1]; }
        if (anyA) {
            if (l0) { atomicAdd(&sA[l0], pack3(e0A.x, e1A.x, e2A.x)); atomicAdd(&sB[l0], packB(e3A.x)); }
            if (l1) { atomicAdd(&sA[l1], pack3(e0A.y, e1A.y, e2A.y)); atomicAdd(&sB[l1], packB(e3A.y)); }
            if (l2) { atomicAdd(&sA[l2], pack3(e0A.z, e1A.z, e2A.z)); atomicAdd(&sB[l2], packB(e3A.z)); }
            if (l3) { atomicAdd(&sA[l3], pack3(e0A.w, e1A.w, e2A.w)); atomicAdd(&sB[l3], packB(e3A.w)); }
        }
        if (anyB) {
            if (l4) { atomicAdd(&sA[l4], pack3(e0B.x, e1B.x, e2B.x)); atomicAdd(&sB[l4], packB(e3B.x)); }
            if (l5) { atomicAdd(&sA[l5], pack3(e0B.y, e1B.y, e2B.y)); atomicAdd(&sB[l5], packB(e3B.y)); }
            if (l6) { atomicAdd(&sA[l6], pack3(e0B.z, e1B.z, e2B.z)); atomicAdd(&sB[l6], packB(e3B.z)); }
            if (l7) { atomicAdd(&sA[l7], pack3(e0B.w, e1B.w, e2B.w)); atomicAdd(&sB[l7], packB(e3B.w)); }
        }
    }
    int rem = NPIX & 3;
    if (rem && chunk == 0 && tid < rem) {
        int i = NG * 4 + tid;
        const int*   ips = inst + (size_t)b * NPIX;
        const float* kps = ker  + (size_t)b * NPIX;
        const float* mps = tmk  + (size_t)b * NPIX;
        int l = (fminf(kps[i], mps[i]) > 0.5f) ? ips[i] : 0;
        if (l) {
            atomicAdd(&sA[l], pack3(ep[i], ep[i + NPIX], ep[i + 2 * NPIX]));
            atomicAdd(&sB[l], packB(ep[i + 3 * NPIX]));
        }
    }
    __syncthreads();
    if (tid >= 1 && tid < LBL) {
        int a0, a1, a2, a3, cnt, dummy;
        unpack3(sA[tid], a0, a1, a2);
        unpack3(sB[tid], a3, cnt, dummy);
        if (cnt) {
            atomicAdd(&g_s01[b * LBL + tid], (ull)(((ll)a1 << 39) + ((ll)a0 << 7)));
            atomicAdd(&g_s23[b * LBL + tid], (ull)(((ll)a3 << 39) + ((ll)a2 << 7)));
            atomicAdd(&g_cnt1[b * LBL + tid], cnt);
        }
    }
    __threadfence();
    __syncthreads();

    // ---------------- device-wide barrier (888 blocks, 6/SM — proven resident)
    if (tid == 0) {
        atomicAdd(&g_bar1, 1u);
        volatile unsigned* vb = &g_bar1;
        while (*vb < (unsigned)gridDim.x) __nanosleep(100);
    }
    __syncthreads();
    __threadfence();

    // ---------------- pass 2: distances to per-label means --------------------
    if (tid < LBL) {
        float m0 = 0.f, m1 = 0.f, m2 = 0.f, m3 = 0.f;
        if (tid > 0) {
            float inv = 1.f / fmaxf((float)g_cnt1[b * LBL + tid], 1.f);
            float a0, a1, a2, a3;
            unpack2_32(g_s01[b * LBL + tid], a0, a1);
            unpack2_32(g_s23[b * LBL + tid], a2, a3);
            m0 = a0 * inv; m1 = a1 * inv; m2 = a2 * inv; m3 = a3 * inv;
        }
        meanv[tid] = make_float4(m0, m1, m2, m3);
    }
    __syncthreads();

    for (int g = gBeg + 2 * tid; g < gEnd; g += 2 * THR) {
        const bool has2 = (g + 1 < gEnd);
        unsigned lmA = __ldcs(glab + g);
        unsigned lmB = has2 ? __ldcs(glab + g + 1) : 0u;
        float4 e0A, e1A, e2A, e3A, e0B, e1B, e2B, e3B;
        if (lmA) { e0A = __ldcs(e0p+g); e1A = __ldcs(e1p+g); e2A = __ldcs(e2p+g); e3A = __ldcs(e3p+g); }
        if (lmB) { e0B = __ldcs(e0p+g+1); e1B = __ldcs(e1p+g+1); e2B = __ldcs(e2p+g+1); e3B = __ldcs(e3p+g+1); }
        #define PAN_PIX(LM, SH, E0, E1, E2, E3)                                \
            {                                                                  \
                int L = (int)((LM >> SH) & 255u);                              \
                if (L) {                                                       \
                    float4 m = meanv[L];                                       \
                    float d0 = E0 - m.x, d1 = E1 - m.y;                        \
                    float d2 = E2 - m.z, d3 = E3 - m.w;                        \
                    float sq = fmaf(d0,d0, fmaf(d1,d1, fmaf(d2,d2, d3*d3)));   \
                    float dist = (sq > 0.f) ? sq * rsqrtf(sq) : 0.f;           \
                    float r = fmaxf(dist - 0.5f, 0.f);                         \
                    float val = __logf(fmaf(r, r, 1.f));                       \
                    unsigned vf = (unsigned)__float2int_rn(val * S_VAL);       \
                    atomicAdd(&sp2[L], ((ull)vf << 22) + 1ull);                \
                }                                                              \
            }
        if (lmA) {
            PAN_PIX(lmA, 0,  e0A.x, e1A.x, e2A.x, e3A.x)
            PAN_PIX(lmA, 8,  e0A.y, e1A.y, e2A.y, e3A.y)
            PAN_PIX(lmA, 16, e0A.z, e1A.z, e2A.z, e3A.z)
            PAN_PIX(lmA, 24, e0A.w, e1A.w, e2A.w, e3A.w)
        }
        if (lmB) {
            PAN_PIX(lmB, 0,  e0B.x, e1B.x, e2B.x, e3B.x)
            PAN_PIX(lmB, 8,  e0B.y, e1B.y, e2B.y, e3B.y)
            PAN_PIX(lmB, 16, e0B.z, e1B.z, e2B.z, e3B.z)
            PAN_PIX(lmB, 24, e0B.w, e1B.w, e2B.w, e3B.w)
        }
        #undef PAN_PIX
    }
    if (rem && chunk == 0 && tid < rem) {
        int i = NG * 4 + tid;
        const int*   ips = inst + (size_t)b * NPIX;
        const float* mps = tmk  + (size_t)b * NPIX;
        int l = (mps[i] > 0.5f) ? ips[i] : 0;
        if (l) {
            float4 m = meanv[l];
            float d0 = ep[i] - m.x, d1 = ep[i+NPIX] - m.y;
            float d2 = ep[i+2*NPIX] - m.z, d3 = ep[i+3*NPIX] - m.w;
            float sq = fmaf(d0,d0, fmaf(d1,d1, fmaf(d2,d2, d3*d3)));
            float dist = (sq > 0.f) ? sq * rsqrtf(sq) : 0.f;
            float r = fmaxf(dist - 0.5f, 0.f);
            unsigned vf = (unsigned)__float2int_rn(__logf(fmaf(r, r, 1.f)) * S_VAL);
            atomicAdd(&sp2[l], ((ull)vf << 22) + 1ull);
        }
    }
    __syncthreads();
    if (tid >= 1 && tid < LBL && sp2[tid]) atomicAdd(&g_p2[b * LBL + tid], sp2[tid]);
    __threadfence();
    __syncthreads();
    if (tid == 0)
        isLast = (atomicAdd(&g_bar2, 1u) == (unsigned)gridDim.x - 1u);
    __syncthreads();
    if (!isLast) return;

    // ---------------- finalize (last block): warp w handles batch w ------------
    __threadfence();
    __shared__ float fm[BMAX][LBL][4];
    const int w = tid >> 5;
    const int l = tid & 31;

    if (w < B) {
        int   ci = g_cnt1[w * LBL + l];
        float c  = (float)ci;
        float m0 = 0.f, m1 = 0.f, m2 = 0.f, m3 = 0.f;
        if (l > 0 && ci > 0) {
            float inv = 1.f / c;
            float a0, a1, a2, a3;
            unpack2_32(g_s01[w * LBL + l], a0, a1);
            unpack2_32(g_s23[w * LBL + l], a2, a3);
            m0 = a0 * inv; m1 = a1 * inv; m2 = a2 * inv; m3 = a3 * inv;
        }
        float csum = (l > 0) ? c : 0.f;
        for (int o = 16; o; o >>= 1) csum += __shfl_xor_sync(0xffffffffu, csum, o);
        if (l == 0) c = (float)NPIX - csum;

        bool present = (c > 0.f);
        unsigned pb = __ballot_sync(0xffffffffu, present);
        int ni = __popc(pb);
        unsigned nzb = pb & ~1u;
        bool nz = present && (l > 0);

        fm[w][l][0] = m0; fm[w][l][1] = m1; fm[w][l][2] = m2; fm[w][l][3] = m3;
        __syncwarp();

        ull p2 = g_p2[w * LBL + l];
        float sv = (float)(double)(p2 >> 22) * INV_S_VAL;
        float ct = (float)(unsigned)(p2 & 0x3FFFFFull);
        float aggl = nz ? sv / fmaxf(ct, 1.f) : 0.f;

        float sq = m0*m0 + m1*m1 + m2*m2 + m3*m3;
        float nrm = (sq > 0.f) ? sqrtf(sq) : 0.f;
        float reg = present ? log1pf(nrm) : 0.f;

        float ds = 0.f, dc = 0.f;
        if (nz) {
            #pragma unroll
            for (int j = 1; j < LBL; j++) {
                if (j != l && ((nzb >> j) & 1u)) {
                    float p0 = m0 - fm[w][j][0];
                    float p1 = m1 - fm[w][j][1];
                    float p2f = m2 - fm[w][j][2];
                    float p3 = m3 - fm[w][j][3];
                    float psq = p0*p0 + p1*p1 + p2f*p2f + p3*p3;
                    float pd = (psq > 0.f) ? sqrtf(psq) : 0.f;
                    float r = fmaxf(3.0f - pd, 0.f);
                    ds += log1pf(r * r);
                    dc += 1.f;
                }
            }
        }
        for (int o = 16; o; o >>= 1) {
            aggl += __shfl_down_sync(0xffffffffu, aggl, o);
            reg  += __shfl_down_sync(0xffffffffu, reg,  o);
            ds   += __shfl_down_sync(0xffffffffu, ds,   o);
            dc   += __shfl_down_sync(0xffffffffu, dc,   o);
        }
        if (l == 0) {
            float l_agg = aggl / (float)((ni - 1) > 1 ? (ni - 1) : 1);
            float l_reg = reg / (float)(ni > 1 ? ni : 1) * 0.001f;
            float l_dis = (ni > 2) ? ds / fmaxf(dc, 1.f) : 0.f;
            out[w] = (ni <= 1) ? 0.f : (l_agg + l_dis + l_reg);
        }
    }
    __syncthreads();
    if (tid < BMAX * LBL) {
        g_s01[tid] = 0ull;
        g_s23[tid] = 0ull;
        g_cnt1[tid] = 0;
        g_p2[tid]  = 0ull;
    }
    if (tid == 0) { g_bar1 = 0u; g_bar2 = 0u; }
}

extern "C" void kernel_launch(void* const* d_in, const int* in_sizes, int n_in,
                              void* d_out, int out_size) {
    const float* emb  = (const float*)d_in[0];
    const int*   inst = (const int*)  d_in[1];
    const float* ker  = (const float*)d_in[2];
    const float* tmk  = (const float*)d_in[3];
    float* out = (float*)d_out;

    int B = out_size;
    if (B > BMAX) B = BMAX;
    int NPIX = in_sizes[1] / B;
    int NG = NPIX >> 2;
    if (NG > NGMAX) NG = NGMAX;   // fixed problem shape: 135424

    // 888 blocks = 148 SMs x 6 — the residency envelope proven in R5-R7
    k_fused<<<B * NCHUNK, THR>>>(emb, inst, ker, tmk, out, NG, NPIX, B);
}

// round 10
// speedup vs baseline: 1.0873x; 1.0873x over previous
#include <cuda_runtime.h>

#define LBL 32
#define BMAX 8
#define THR 256
#define NCHUNK 111       // chunks per batch -> grid = 8*111 = 888 = 148 SMs x 6
#define NGMAX 135424     // 736*736/4
typedef unsigned long long ull;
typedef long long ll;

#define S_EMB 65536.f
#define INV_S_EMB (1.f/65536.f)
#define S_VAL 262144.f
#define INV_S_VAL (1.f/262144.f)
#define S_LOC 512.f      // 2^9 local fixed-point scale (21-bit fields)

// global scratch (zeroed at module load; finalize re-zeros for next graph replay)
__device__ ull g_s01[BMAX * LBL];   // packed 32.32 (sum_e0, sum_e1)
__device__ ull g_s23[BMAX * LBL];   // packed 32.32 (sum_e2, sum_e3)
__device__ int g_cnt1[BMAX * LBL];  // kernel-region counts
__device__ ull g_p2[BMAX * LBL];    // packed (sum_val<<22) + cnt
__device__ unsigned g_bar1, g_bar2;
__device__ unsigned g_lab[BMAX * NGMAX];  // pass1->pass2 cached mask-labels (4x u8)

__device__ __forceinline__ void unpack2_32(ull p, float& a, float& b) {
    ll P = (ll)p;
    int ia = (int)(unsigned)(P & 0xFFFFFFFFll);
    int ib = (int)((P - (ll)ia) >> 32);
    a = (float)ia * INV_S_EMB;
    b = (float)ib * INV_S_EMB;
}
// 3x21-bit signed fields; exact borrow recovery (|field| < 2^20)
__device__ __forceinline__ ull pack3(float a, float b, float c) {
    return (ull)((ll)__float2int_rn(a * S_LOC)
               + ((ll)__float2int_rn(b * S_LOC) << 21)
               + ((ll)__float2int_rn(c * S_LOC) << 42));
}
__device__ __forceinline__ ull packB(float e3) {
    return (ull)((ll)__float2int_rn(e3 * S_LOC) + (1ll << 21));
}
__device__ __forceinline__ void unpack3(ull p, int& x, int& y, int& z) {
    ll P = (ll)p;
    x = (int)((P << 43) >> 43); P = (P - (ll)x) >> 21;
    y = (int)((P << 43) >> 43); P = (P - (ll)y) >> 21;
    z = (int)P;
}

__global__ void __launch_bounds__(THR, 6) k_fused(
    const float* __restrict__ emb, const int* __restrict__ inst,
    const float* __restrict__ ker, const float* __restrict__ tmk,
    float* __restrict__ out, int NG, int NPIX, int B)
{
    const int tid   = threadIdx.x;
    const int b     = blockIdx.x % B;
    const int chunk = blockIdx.x / B;
    const int CS    = (NG + NCHUNK - 1) / NCHUNK;
    const int gBeg  = chunk * CS;
    const int gEnd  = (gBeg + CS < NG) ? gBeg + CS : NG;

    __shared__ ull sA[LBL], sB[LBL], sp2[LBL];
    __shared__ float4 meanv[LBL];
    __shared__ int isLast;

    if (tid < LBL) { sA[tid] = 0ull; sB[tid] = 0ull; sp2[tid] = 0ull; }
    __syncthreads();

    const int4*   ip  = (const int4*)  (inst + (size_t)b * NPIX);
    const float4* kp  = (const float4*)(ker  + (size_t)b * NPIX);
    const float4* mp  = (const float4*)(tmk  + (size_t)b * NPIX);
    const float*  ep  = emb + (size_t)b * 4 * NPIX;
    const float4* e0p = (const float4*)(ep);
    const float4* e1p = (const float4*)(ep + NPIX);
    const float4* e2p = (const float4*)(ep + 2 * NPIX);
    const float4* e3p = (const float4*)(ep + 3 * NPIX);
    unsigned* glab = g_lab + (size_t)b * NGMAX;

    // ---------------- pass 1: kernel sums + label cache for pass 2 ------------
    // 2x unroll: thread t handles (gg+tid) and (gg+tid+THR) — both coalesced.
    for (int gg = gBeg; gg < gEnd; gg += 2 * THR) {
        const int gA = gg + tid;
        const int gB = gA + THR;
        const bool vA = gA < gEnd;
        const bool vB = gB < gEnd;

        int4 lbA, lbB; float4 kvA, mvA, kvB, mvB;
        if (vA) { lbA = ip[gA]; kvA = kp[gA]; mvA = mp[gA]; }
        if (vB) { lbB = ip[gB]; kvB = kp[gB]; mvB = mp[gB]; }

        int l0=0,l1=0,l2=0,l3=0,l4=0,l5=0,l6=0,l7=0;
        if (vA) {
            int lm0 = (mvA.x > 0.5f) ? lbA.x : 0;
            int lm1 = (mvA.y > 0.5f) ? lbA.y : 0;
            int lm2 = (mvA.z > 0.5f) ? lbA.z : 0;
            int lm3 = (mvA.w > 0.5f) ? lbA.w : 0;
            glab[gA] = (unsigned)lm0 | ((unsigned)lm1 << 8) | ((unsigned)lm2 << 16) | ((unsigned)lm3 << 24);
            l0 = (kvA.x > 0.5f) ? lm0 : 0;
            l1 = (kvA.y > 0.5f) ? lm1 : 0;
            l2 = (kvA.z > 0.5f) ? lm2 : 0;
            l3 = (kvA.w > 0.5f) ? lm3 : 0;
        }
        if (vB) {
            int lm4 = (mvB.x > 0.5f) ? lbB.x : 0;
            int lm5 = (mvB.y > 0.5f) ? lbB.y : 0;
            int lm6 = (mvB.z > 0.5f) ? lbB.z : 0;
            int lm7 = (mvB.w > 0.5f) ? lbB.w : 0;
            glab[gB] = (unsigned)lm4 | ((unsigned)lm5 << 8) | ((unsigned)lm6 << 16) | ((unsigned)lm7 << 24);
            l4 = (kvB.x > 0.5f) ? lm4 : 0;
            l5 = (kvB.y > 0.5f) ? lm5 : 0;
            l6 = (kvB.z > 0.5f) ? lm6 : 0;
            l7 = (kvB.w > 0.5f) ? lm7 : 0;
        }

        const bool anyA = (l0 | l1 | l2 | l3) != 0;
        const bool anyB = (l4 | l5 | l6 | l7) != 0;
        float4 e0A, e1A, e2A, e3A, e0B, e1B, e2B, e3B;
        if (anyA) { e0A = e0p[gA]; e1A = e1p[gA]; e2A = e2p[gA]; e3A = e3p[gA]; }
        if (anyB) { e0B = e0p[gB]; e1B = e1p[gB]; e2B = e2p[gB]; e3B = e3p[gB]; }
        if (anyA) {
            if (l0) { atomicAdd(&sA[l0], pack3(e0A.x, e1A.x, e2A.x)); atomicAdd(&sB[l0], packB(e3A.x)); }
            if (l1) { atomicAdd(&sA[l1], pack3(e0A.y, e1A.y, e2A.y)); atomicAdd(&sB[l1], packB(e3A.y)); }
            if (l2) { atomicAdd(&sA[l2], pack3(e0A.z, e1A.z, e2A.z)); atomicAdd(&sB[l2], packB(e3A.z)); }
            if (l3) { atomicAdd(&sA[l3], pack3(e0A.w, e1A.w, e2A.w)); atomicAdd(&sB[l3], packB(e3A.w)); }
        }
        if (anyB) {
            if (l4) { atomicAdd(&sA[l4], pack3(e0B.x, e1B.x, e2B.x)); atomicAdd(&sB[l4], packB(e3B.x)); }
            if (l5) { atomicAdd(&sA[l5], pack3(e0B.y, e1B.y, e2B.y)); atomicAdd(&sB[l5], packB(e3B.y)); }
            if (l6) { atomicAdd(&sA[l6], pack3(e0B.z, e1B.z, e2B.z)); atomicAdd(&sB[l6], packB(e3B.z)); }
            if (l7) { atomicAdd(&sA[l7], pack3(e0B.w, e1B.w, e2B.w)); atomicAdd(&sB[l7], packB(e3B.w)); }
        }
    }
    int rem = NPIX & 3;
    if (rem && chunk == 0 && tid < rem) {
        int i = NG * 4 + tid;
        const int*   ips = inst + (size_t)b * NPIX;
        const float* kps = ker  + (size_t)b * NPIX;
        const float* mps = tmk  + (size_t)b * NPIX;
        int l = (fminf(kps[i], mps[i]) > 0.5f) ? ips[i] : 0;
        if (l) {
            atomicAdd(&sA[l], pack3(ep[i], ep[i + NPIX], ep[i + 2 * NPIX]));
            atomicAdd(&sB[l], packB(ep[i + 3 * NPIX]));
        }
    }
    __syncthreads();
    if (tid >= 1 && tid < LBL) {
        int a0, a1, a2, a3, cnt, dummy;
        unpack3(sA[tid], a0, a1, a2);
        unpack3(sB[tid], a3, cnt, dummy);
        if (cnt) {
            atomicAdd(&g_s01[b * LBL + tid], (ull)(((ll)a1 << 39) + ((ll)a0 << 7)));
            atomicAdd(&g_s23[b * LBL + tid], (ull)(((ll)a3 << 39) + ((ll)a2 << 7)));
            atomicAdd(&g_cnt1[b * LBL + tid], cnt);
        }
    }
    __threadfence();
    __syncthreads();

    // ---------------- device-wide barrier (888 blocks, 6/SM — proven resident)
    if (tid == 0) {
        atomicAdd(&g_bar1, 1u);
        volatile unsigned* vb = &g_bar1;
        while (*vb < (unsigned)gridDim.x) __nanosleep(100);
    }
    __syncthreads();
    __threadfence();

    // ---------------- pass 2: distances to per-label means --------------------
    if (tid < LBL) {
        float m0 = 0.f, m1 = 0.f, m2 = 0.f, m3 = 0.f;
        if (tid > 0) {
            float inv = 1.f / fmaxf((float)g_cnt1[b * LBL + tid], 1.f);
            float a0, a1, a2, a3;
            unpack2_32(g_s01[b * LBL + tid], a0, a1);
            unpack2_32(g_s23[b * LBL + tid], a2, a3);
            m0 = a0 * inv; m1 = a1 * inv; m2 = a2 * inv; m3 = a3 * inv;
        }
        meanv[tid] = make_float4(m0, m1, m2, m3);
    }
    __syncthreads();

    for (int gg = gBeg; gg < gEnd; gg += 2 * THR) {
        const int gA = gg + tid;
        const int gB = gA + THR;
        unsigned lmA = (gA < gEnd) ? glab[gA] : 0u;
        unsigned lmB = (gB < gEnd) ? glab[gB] : 0u;
        float4 e0A, e1A, e2A, e3A, e0B, e1B, e2B, e3B;
        if (lmA) { e0A = e0p[gA]; e1A = e1p[gA]; e2A = e2p[gA]; e3A = e3p[gA]; }
        if (lmB) { e0B = e0p[gB]; e1B = e1p[gB]; e2B = e2p[gB]; e3B = e3p[gB]; }
        #define PAN_PIX(LM, SH, E0, E1, E2, E3)                                \
            {                                                                  \
                int L = (int)((LM >> SH) & 255u);                              \
                if (L) {                                                       \
                    float4 m = meanv[L];                                       \
                    float d0 = E0 - m.x, d1 = E1 - m.y;                        \
                    float d2 = E2 - m.z, d3 = E3 - m.w;                        \
                    float sq = fmaf(d0,d0, fmaf(d1,d1, fmaf(d2,d2, d3*d3)));   \
                    float dist = (sq > 0.f) ? sq * rsqrtf(sq) : 0.f;           \
                    float r = fmaxf(dist - 0.5f, 0.f);                         \
                    float val = __logf(fmaf(r, r, 1.f));                       \
                    unsigned vf = (unsigned)__float2int_rn(val * S_VAL);       \
                    atomicAdd(&sp2[L], ((ull)vf << 22) + 1ull);                \
                }                                                              \
            }
        if (lmA) {
            PAN_PIX(lmA, 0,  e0A.x, e1A.x, e2A.x, e3A.x)
            PAN_PIX(lmA, 8,  e0A.y, e1A.y, e2A.y, e3A.y)
            PAN_PIX(lmA, 16, e0A.z, e1A.z, e2A.z, e3A.z)
            PAN_PIX(lmA, 24, e0A.w, e1A.w, e2A.w, e3A.w)
        }
        if (lmB) {
            PAN_PIX(lmB, 0,  e0B.x, e1B.x, e2B.x, e3B.x)
            PAN_PIX(lmB, 8,  e0B.y, e1B.y, e2B.y, e3B.y)
            PAN_PIX(lmB, 16, e0B.z, e1B.z, e2B.z, e3B.z)
            PAN_PIX(lmB, 24, e0B.w, e1B.w, e2B.w, e3B.w)
        }
        #undef PAN_PIX
    }
    if (rem && chunk == 0 && tid < rem) {
        int i = NG * 4 + tid;
        const int*   ips = inst + (size_t)b * NPIX;
        const float* mps = tmk  + (size_t)b * NPIX;
        int l = (mps[i] > 0.5f) ? ips[i] : 0;
        if (l) {
            float4 m = meanv[l];
            float d0 = ep[i] - m.x, d1 = ep[i+NPIX] - m.y;
            float d2 = ep[i+2*NPIX] - m.z, d3 = ep[i+3*NPIX] - m.w;
            float sq = fmaf(d0,d0, fmaf(d1,d1, fmaf(d2,d2, d3*d3)));
            float dist = (sq > 0.f) ? sq * rsqrtf(sq) : 0.f;
            float r = fmaxf(dist - 0.5f, 0.f);
            unsigned vf = (unsigned)__float2int_rn(__logf(fmaf(r, r, 1.f)) * S_VAL);
            atomicAdd(&sp2[l], ((ull)vf << 22) + 1ull);
        }
    }
    __syncthreads();
    if (tid >= 1 && tid < LBL && sp2[tid]) atomicAdd(&g_p2[b * LBL + tid], sp2[tid]);
    __threadfence();
    __syncthreads();
    if (tid == 0)
        isLast = (atomicAdd(&g_bar2, 1u) == (unsigned)gridDim.x - 1u);
    __syncthreads();
    if (!isLast) return;

    // ---------------- finalize (last block): warp w handles batch w ------------
    __threadfence();
    __shared__ float fm[BMAX][LBL][4];
    const int w = tid >> 5;
    const int l = tid & 31;

    if (w < B) {
        int   ci = g_cnt1[w * LBL + l];
        float c  = (float)ci;
        float m0 = 0.f, m1 = 0.f, m2 = 0.f, m3 = 0.f;
        if (l > 0 && ci > 0) {
            float inv = 1.f / c;
            float a0, a1, a2, a3;
            unpack2_32(g_s01[w * LBL + l], a0, a1);
            unpack2_32(g_s23[w * LBL + l], a2, a3);
            m0 = a0 * inv; m1 = a1 * inv; m2 = a2 * inv; m3 = a3 * inv;
        }
        float csum = (l > 0) ? c : 0.f;
        for (int o = 16; o; o >>= 1) csum += __shfl_xor_sync(0xffffffffu, csum, o);
        if (l == 0) c = (float)NPIX - csum;

        bool present = (c > 0.f);
        unsigned pb = __ballot_sync(0xffffffffu, present);
        int ni = __popc(pb);
        unsigned nzb = pb & ~1u;
        bool nz = present && (l > 0);

        fm[w][l][0] = m0; fm[w][l][1] = m1; fm[w][l][2] = m2; fm[w][l][3] = m3;
        __syncwarp();

        ull p2 = g_p2[w * LBL + l];
        float sv = (float)(double)(p2 >> 22) * INV_S_VAL;
        float ct = (float)(unsigned)(p2 & 0x3FFFFFull);
        float aggl = nz ? sv / fmaxf(ct, 1.f) : 0.f;

        float sq = m0*m0 + m1*m1 + m2*m2 + m3*m3;
        float nrm = (sq > 0.f) ? sqrtf(sq) : 0.f;
        float reg = present ? log1pf(nrm) : 0.f;

        float ds = 0.f, dc = 0.f;
        if (nz) {
            #pragma unroll
            for (int j = 1; j < LBL; j++) {
                if (j != l && ((nzb >> j) & 1u)) {
                    float p0 = m0 - fm[w][j][0];
                    float p1 = m1 - fm[w][j][1];
                    float p2f = m2 - fm[w][j][2];
                    float p3 = m3 - fm[w][j][3];
                    float psq = p0*p0 + p1*p1 + p2f*p2f + p3*p3;
                    float pd = (psq > 0.f) ? sqrtf(psq) : 0.f;
                    float r = fmaxf(3.0f - pd, 0.f);
                    ds += log1pf(r * r);
                    dc += 1.f;
                }
            }
        }
        for (int o = 16; o; o >>= 1) {
            aggl += __shfl_down_sync(0xffffffffu, aggl, o);
            reg  += __shfl_down_sync(0xffffffffu, reg,  o);
            ds   += __shfl_down_sync(0xffffffffu, ds,   o);
            dc   += __shfl_down_sync(0xffffffffu, dc,   o);
        }
        if (l == 0) {
            float l_agg = aggl / (float)((ni - 1) > 1 ? (ni - 1) : 1);
            float l_reg = reg / (float)(ni > 1 ? ni : 1) * 0.001f;
            float l_dis = (ni > 2) ? ds / fmaxf(dc, 1.f) : 0.f;
            out[w] = (ni <= 1) ? 0.f : (l_agg + l_dis + l_reg);
        }
    }
    __syncthreads();
    if (tid < BMAX * LBL) {
        g_s01[tid] = 0ull;
        g_s23[tid] = 0ull;
        g_cnt1[tid] = 0;
        g_p2[tid]  = 0ull;
    }
    if (tid == 0) { g_bar1 = 0u; g_bar2 = 0u; }
}

extern "C" void kernel_launch(void* const* d_in, const int* in_sizes, int n_in,
                              void* d_out, int out_size) {
    const float* emb  = (const float*)d_in[0];
    const int*   inst = (const int*)  d_in[1];
    const float* ker  = (const float*)d_in[2];
    const float* tmk  = (const float*)d_in[3];
    float* out = (float*)d_out;

    int B = out_size;
    if (B > BMAX) B = BMAX;
    int NPIX = in_sizes[1] / B;
    int NG = NPIX >> 2;
    if (NG > NGMAX) NG = NGMAX;   // fixed problem shape: 135424

    // 888 blocks = 148 SMs x 6 — the residency envelope proven in R5-R7
    k_fused<<<B * NCHUNK, THR>>>(emb, inst, ker, tmk, out, NG, NPIX, B);
}

// round 11
// speedup vs baseline: 1.4890x; 1.3695x over previous
#include <cuda_runtime.h>

#define LBL 32
#define BMAX 8
#define THR 256
#define NCHUNK 111       // chunks per batch -> grid = 8*111 = 888 = 148 SMs x 6
#define NGMAX 135424     // 736*736/4
typedef unsigned long long ull;
typedef long long ll;

#define S_EMB 65536.f
#define INV_S_EMB (1.f/65536.f)
#define S_VAL 262144.f
#define INV_S_VAL (1.f/262144.f)
#define S_LOC 512.f      // 2^9 local fixed-point scale (21-bit fields)

// global scratch (zeroed at module load; finalize re-zeros for next graph replay)
__device__ ull g_s01[BMAX * LBL];   // packed 32.32 (sum_e0, sum_e1)
__device__ ull g_s23[BMAX * LBL];   // packed 32.32 (sum_e2, sum_e3)
__device__ int g_cnt1[BMAX * LBL];  // kernel-region counts
__device__ ull g_p2[BMAX * LBL];    // packed (sum_val<<22) + cnt
__device__ unsigned g_bar1, g_bar2;
__device__ unsigned g_lab[BMAX * NGMAX];  // pass1->pass2 cached mask-labels (4x u8)

__device__ __forceinline__ void unpack2_32(ull p, float& a, float& b) {
    ll P = (ll)p;
    int ia = (int)(unsigned)(P & 0xFFFFFFFFll);
    int ib = (int)((P - (ll)ia) >> 32);
    a = (float)ia * INV_S_EMB;
    b = (float)ib * INV_S_EMB;
}
// 3x21-bit signed fields; exact borrow recovery (|field| < 2^20)
__device__ __forceinline__ ull pack3(float a, float b, float c) {
    return (ull)((ll)__float2int_rn(a * S_LOC)
               + ((ll)__float2int_rn(b * S_LOC) << 21)
               + ((ll)__float2int_rn(c * S_LOC) << 42));
}
__device__ __forceinline__ ull packB(float e3) {
    return (ull)((ll)__float2int_rn(e3 * S_LOC) + (1ll << 21));
}
__device__ __forceinline__ void unpack3(ull p, int& x, int& y, int& z) {
    ll P = (ll)p;
    x = (int)((P << 43) >> 43); P = (P - (ll)x) >> 21;
    y = (int)((P << 43) >> 43); P = (P - (ll)y) >> 21;
    z = (int)P;
}

__global__ void __launch_bounds__(THR, 6) k_fused(
    const float* __restrict__ emb, const int* __restrict__ inst,
    const float* __restrict__ ker, const float* __restrict__ tmk,
    float* __restrict__ out, int NG, int NPIX, int B)
{
    const int tid   = threadIdx.x;
    const int b     = blockIdx.x % B;
    const int chunk = blockIdx.x / B;
    const int CS    = (NG + NCHUNK - 1) / NCHUNK;
    const int gBeg  = chunk * CS;
    const int gEnd  = (gBeg + CS < NG) ? gBeg + CS : NG;

    __shared__ ull sA[LBL], sB[LBL], sp2[LBL];
    __shared__ float4 meanv[LBL];
    __shared__ int isLast;

    if (tid < LBL) { sA[tid] = 0ull; sB[tid] = 0ull; sp2[tid] = 0ull; }
    __syncthreads();

    const int4*   ip  = (const int4*)  (inst + (size_t)b * NPIX);
    const float4* kp  = (const float4*)(ker  + (size_t)b * NPIX);
    const float4* mp  = (const float4*)(tmk  + (size_t)b * NPIX);
    const float*  ep  = emb + (size_t)b * 4 * NPIX;
    const float4* e0p = (const float4*)(ep);
    const float4* e1p = (const float4*)(ep + NPIX);
    const float4* e2p = (const float4*)(ep + 2 * NPIX);
    const float4* e3p = (const float4*)(ep + 3 * NPIX);
    unsigned* glab = g_lab + (size_t)b * NGMAX;

    // ---------------- pass 1: kernel sums + label cache for pass 2 ------------
    // mask streams are single-use -> __ldcs (evict-first) so emb stays in L2
    for (int g = gBeg + tid; g < gEnd; g += THR) {
        int4   lb = __ldcs(ip + g);
        float4 kv = __ldcs(kp + g);
        float4 mv = __ldcs(mp + g);
        int lm0 = (mv.x > 0.5f) ? lb.x : 0;
        int lm1 = (mv.y > 0.5f) ? lb.y : 0;
        int lm2 = (mv.z > 0.5f) ? lb.z : 0;
        int lm3 = (mv.w > 0.5f) ? lb.w : 0;
        glab[g] = (unsigned)lm0 | ((unsigned)lm1 << 8) | ((unsigned)lm2 << 16) | ((unsigned)lm3 << 24);
        int l0 = (kv.x > 0.5f) ? lm0 : 0;
        int l1 = (kv.y > 0.5f) ? lm1 : 0;
        int l2 = (kv.z > 0.5f) ? lm2 : 0;
        int l3 = (kv.w > 0.5f) ? lm3 : 0;
        if ((l0 | l1 | l2 | l3) != 0) {
            float4 e0 = e0p[g], e1 = e1p[g], e2 = e2p[g], e3 = e3p[g];
            if (l0) { atomicAdd(&sA[l0], pack3(e0.x, e1.x, e2.x)); atomicAdd(&sB[l0], packB(e3.x)); }
            if (l1) { atomicAdd(&sA[l1], pack3(e0.y, e1.y, e2.y)); atomicAdd(&sB[l1], packB(e3.y)); }
            if (l2) { atomicAdd(&sA[l2], pack3(e0.z, e1.z, e2.z)); atomicAdd(&sB[l2], packB(e3.z)); }
            if (l3) { atomicAdd(&sA[l3], pack3(e0.w, e1.w, e2.w)); atomicAdd(&sB[l3], packB(e3.w)); }
        }
    }
    int rem = NPIX & 3;
    if (rem && chunk == 0 && tid < rem) {
        int i = NG * 4 + tid;
        const int*   ips = inst + (size_t)b * NPIX;
        const float* kps = ker  + (size_t)b * NPIX;
        const float* mps = tmk  + (size_t)b * NPIX;
        int l = (fminf(kps[i], mps[i]) > 0.5f) ? ips[i] : 0;
        if (l) {
            atomicAdd(&sA[l], pack3(ep[i], ep[i + NPIX], ep[i + 2 * NPIX]));
            atomicAdd(&sB[l], packB(ep[i + 3 * NPIX]));
        }
    }
    __syncthreads();
    if (tid >= 1 && tid < LBL) {
        int a0, a1, a2, a3, cnt, dummy;
        unpack3(sA[tid], a0, a1, a2);
        unpack3(sB[tid], a3, cnt, dummy);
        if (cnt) {
            atomicAdd(&g_s01[b * LBL + tid], (ull)(((ll)a1 << 39) + ((ll)a0 << 7)));
            atomicAdd(&g_s23[b * LBL + tid], (ull)(((ll)a3 << 39) + ((ll)a2 << 7)));
            atomicAdd(&g_cnt1[b * LBL + tid], cnt);
        }
    }
    __threadfence();
    __syncthreads();

    // ---------------- device-wide barrier (888 blocks, 6/SM — proven resident)
    if (tid == 0) {
        atomicAdd(&g_bar1, 1u);
        volatile unsigned* vb = &g_bar1;
        while (*vb < (unsigned)gridDim.x) __nanosleep(100);
    }
    __syncthreads();
    __threadfence();

    // ---------------- pass 2: distances to per-label means --------------------
    if (tid < LBL) {
        float m0 = 0.f, m1 = 0.f, m2 = 0.f, m3 = 0.f;
        if (tid > 0) {
            float inv = 1.f / fmaxf((float)g_cnt1[b * LBL + tid], 1.f);
            float a0, a1, a2, a3;
            unpack2_32(g_s01[b * LBL + tid], a0, a1);
            unpack2_32(g_s23[b * LBL + tid], a2, a3);
            m0 = a0 * inv; m1 = a1 * inv; m2 = a2 * inv; m3 = a3 * inv;
        }
        meanv[tid] = make_float4(m0, m1, m2, m3);
    }
    __syncthreads();

    // REVERSE traversal: most-recently-read emb lines re-read first (LRU-friendly)
    const int nIter = (gEnd - gBeg + THR - 1) / THR;
    for (int it = nIter - 1; it >= 0; --it) {
        const int g = gBeg + it * THR + tid;
        if (g >= gEnd) continue;
        unsigned lm = glab[g];
        if (lm != 0u) {
            float4 e0 = e0p[g], e1 = e1p[g], e2 = e2p[g], e3 = e3p[g];
            #define PAN_PIX(SH, X)                                             \
                {                                                              \
                    int L = (int)((lm >> SH) & 255u);                          \
                    if (L) {                                                   \
                        float4 m = meanv[L];                                   \
                        float d0 = e0.X - m.x, d1 = e1.X - m.y;                \
                        float d2 = e2.X - m.z, d3 = e3.X - m.w;                \
                        float sq = fmaf(d0,d0, fmaf(d1,d1, fmaf(d2,d2, d3*d3)));\
                        float dist = (sq > 0.f) ? sq * rsqrtf(sq) : 0.f;       \
                        float r = fmaxf(dist - 0.5f, 0.f);                     \
                        float val = __logf(fmaf(r, r, 1.f));                   \
                        unsigned vf = (unsigned)__float2int_rn(val * S_VAL);   \
                        atomicAdd(&sp2[L], ((ull)vf << 22) + 1ull);            \
                    }                                                          \
                }
            PAN_PIX(0, x) PAN_PIX(8, y) PAN_PIX(16, z) PAN_PIX(24, w)
            #undef PAN_PIX
        }
    }
    if (rem && chunk == 0 && tid < rem) {
        int i = NG * 4 + tid;
        const int*   ips = inst + (size_t)b * NPIX;
        const float* mps = tmk  + (size_t)b * NPIX;
        int l = (mps[i] > 0.5f) ? ips[i] : 0;
        if (l) {
            float4 m = meanv[l];
            float d0 = ep[i] - m.x, d1 = ep[i+NPIX] - m.y;
            float d2 = ep[i+2*NPIX] - m.z, d3 = ep[i+3*NPIX] - m.w;
            float sq = fmaf(d0,d0, fmaf(d1,d1, fmaf(d2,d2, d3*d3)));
            float dist = (sq > 0.f) ? sq * rsqrtf(sq) : 0.f;
            float r = fmaxf(dist - 0.5f, 0.f);
            unsigned vf = (unsigned)__float2int_rn(__logf(fmaf(r, r, 1.f)) * S_VAL);
            atomicAdd(&sp2[l], ((ull)vf << 22) + 1ull);
        }
    }
    __syncthreads();
    if (tid >= 1 && tid < LBL && sp2[tid]) atomicAdd(&g_p2[b * LBL + tid], sp2[tid]);
    __threadfence();
    __syncthreads();
    if (tid == 0)
        isLast = (atomicAdd(&g_bar2, 1u) == (unsigned)gridDim.x - 1u);
    __syncthreads();
    if (!isLast) return;

    // ---------------- finalize (last block): warp w handles batch w ------------
    __threadfence();
    __shared__ float fm[BMAX][LBL][4];
    const int w = tid >> 5;
    const int l = tid & 31;

    if (w < B) {
        int   ci = g_cnt1[w * LBL + l];
        float c  = (float)ci;
        float m0 = 0.f, m1 = 0.f, m2 = 0.f, m3 = 0.f;
        if (l > 0 && ci > 0) {
            float inv = 1.f / c;
            float a0, a1, a2, a3;
            unpack2_32(g_s01[w * LBL + l], a0, a1);
            unpack2_32(g_s23[w * LBL + l], a2, a3);
            m0 = a0 * inv; m1 = a1 * inv; m2 = a2 * inv; m3 = a3 * inv;
        }
        float csum = (l > 0) ? c : 0.f;
        for (int o = 16; o; o >>= 1) csum += __shfl_xor_sync(0xffffffffu, csum, o);
        if (l == 0) c = (float)NPIX - csum;

        bool present = (c > 0.f);
        unsigned pb = __ballot_sync(0xffffffffu, present);
        int ni = __popc(pb);
        unsigned nzb = pb & ~1u;
        bool nz = present && (l > 0);

        fm[w][l][0] = m0; fm[w][l][1] = m1; fm[w][l][2] = m2; fm[w][l][3] = m3;
        __syncwarp();

        ull p2 = g_p2[w * LBL + l];
        float sv = (float)(double)(p2 >> 22) * INV_S_VAL;
        float ct = (float)(unsigned)(p2 & 0x3FFFFFull);
        float aggl = nz ? sv / fmaxf(ct, 1.f) : 0.f;

        float sq = m0*m0 + m1*m1 + m2*m2 + m3*m3;
        float nrm = (sq > 0.f) ? sqrtf(sq) : 0.f;
        float reg = present ? log1pf(nrm) : 0.f;

        float ds = 0.f, dc = 0.f;
        if (nz) {
            #pragma unroll
            for (int j = 1; j < LBL; j++) {
                if (j != l && ((nzb >> j) & 1u)) {
                    float p0 = m0 - fm[w][j][0];
                    float p1 = m1 - fm[w][j][1];
                    float p2f = m2 - fm[w][j][2];
                    float p3 = m3 - fm[w][j][3];
                    float psq = p0*p0 + p1*p1 + p2f*p2f + p3*p3;
                    float pd = (psq > 0.f) ? sqrtf(psq) : 0.f;
                    float r = fmaxf(3.0f - pd, 0.f);
                    ds += log1pf(r * r);
                    dc += 1.f;
                }
            }
        }
        for (int o = 16; o; o >>= 1) {
            aggl += __shfl_down_sync(0xffffffffu, aggl, o);
            reg  += __shfl_down_sync(0xffffffffu, reg,  o);
            ds   += __shfl_down_sync(0xffffffffu, ds,   o);
            dc   += __shfl_down_sync(0xffffffffu, dc,   o);
        }
        if (l == 0) {
            float l_agg = aggl / (float)((ni - 1) > 1 ? (ni - 1) : 1);
            float l_reg = reg / (float)(ni > 1 ? ni : 1) * 0.001f;
            float l_dis = (ni > 2) ? ds / fmaxf(dc, 1.f) : 0.f;
            out[w] = (ni <= 1) ? 0.f : (l_agg + l_dis + l_reg);
        }
    }
    __syncthreads();
    if (tid < BMAX * LBL) {
        g_s01[tid] = 0ull;
        g_s23[tid] = 0ull;
        g_cnt1[tid] = 0;
        g_p2[tid]  = 0ull;
    }
    if (tid == 0) { g_bar1 = 0u; g_bar2 = 0u; }
}

extern "C" void kernel_launch(void* const* d_in, const int* in_sizes, int n_in,
                              void* d_out, int out_size) {
    const float* emb  = (const float*)d_in[0];
    const int*   inst = (const int*)  d_in[1];
    const float* ker  = (const float*)d_in[2];
    const float* tmk  = (const float*)d_in[3];
    float* out = (float*)d_out;

    int B = out_size;
    if (B > BMAX) B = BMAX;
    int NPIX = in_sizes[1] / B;
    int NG = NPIX >> 2;
    if (NG > NGMAX) NG = NGMAX;   // fixed problem shape: 135424

    // 888 blocks = 148 SMs x 6 — the residency envelope proven in R5-R7
    k_fused<<<B * NCHUNK, THR>>>(emb, inst, ker, tmk, out, NG, NPIX, B);
}

// round 12
// speedup vs baseline: 1.5585x; 1.0467x over previous
#include <cuda_runtime.h>

#define LBL 32
#define BMAX 8
#define THR 256
#define NCHUNK 111       // chunks per batch -> grid = 8*111 = 888 = 148 SMs x 6
#define NGMAX 135424     // 736*736/4
typedef unsigned long long ull;
typedef long long ll;

#define S_EMB 65536.f
#define INV_S_EMB (1.f/65536.f)
#define S_VAL 262144.f
#define INV_S_VAL (1.f/262144.f)
#define S_LOC 512.f      // 2^9 local fixed-point scale (21-bit fields)

// global scratch (zeroed at module load; finalize re-zeros for next graph replay)
__device__ ull g_s01[BMAX * LBL];   // packed 32.32 (sum_e0, sum_e1)
__device__ ull g_s23[BMAX * LBL];   // packed 32.32 (sum_e2, sum_e3)
__device__ int g_cnt1[BMAX * LBL];  // kernel-region counts
__device__ ull g_p2[BMAX * LBL];    // packed (sum_val<<22) + cnt
__device__ unsigned g_bar1, g_bar2;
__device__ unsigned g_lab[BMAX * NGMAX];  // pass1->pass2 cached mask-labels (4x u8)

__device__ __forceinline__ void unpack2_32(ull p, float& a, float& b) {
    ll P = (ll)p;
    int ia = (int)(unsigned)(P & 0xFFFFFFFFll);
    int ib = (int)((P - (ll)ia) >> 32);
    a = (float)ia * INV_S_EMB;
    b = (float)ib * INV_S_EMB;
}
// 3x21-bit signed fields; exact borrow recovery (|field| < 2^20)
__device__ __forceinline__ ull pack3(float a, float b, float c) {
    return (ull)((ll)__float2int_rn(a * S_LOC)
               + ((ll)__float2int_rn(b * S_LOC) << 21)
               + ((ll)__float2int_rn(c * S_LOC) << 42));
}
__device__ __forceinline__ ull packB(float e3) {
    return (ull)((ll)__float2int_rn(e3 * S_LOC) + (1ll << 21));
}
__device__ __forceinline__ void unpack3(ull p, int& x, int& y, int& z) {
    ll P = (ll)p;
    x = (int)((P << 43) >> 43); P = (P - (ll)x) >> 21;
    y = (int)((P << 43) >> 43); P = (P - (ll)y) >> 21;
    z = (int)P;
}

__global__ void __launch_bounds__(THR, 6) k_fused(
    const float* __restrict__ emb, const int* __restrict__ inst,
    const float* __restrict__ ker, const float* __restrict__ tmk,
    float* __restrict__ out, int NG, int NPIX, int B)
{
    const int tid   = threadIdx.x;
    const int b     = blockIdx.x % B;
    const int chunk = blockIdx.x / B;
    const int CS    = (NG + NCHUNK - 1) / NCHUNK;
    const int gBeg  = chunk * CS;
    const int gEnd  = (gBeg + CS < NG) ? gBeg + CS : NG;

    __shared__ ull sA[LBL], sB[LBL], sp2[LBL];
    __shared__ float4 meanv[LBL];
    __shared__ int isLast;

    if (tid < LBL) { sA[tid] = 0ull; sB[tid] = 0ull; sp2[tid] = 0ull; }
    __syncthreads();

    const int4*   ip  = (const int4*)  (inst + (size_t)b * NPIX);
    const float4* kp  = (const float4*)(ker  + (size_t)b * NPIX);
    const float4* mp  = (const float4*)(tmk  + (size_t)b * NPIX);
    const float*  ep  = emb + (size_t)b * 4 * NPIX;
    const float4* e0p = (const float4*)(ep);
    const float4* e1p = (const float4*)(ep + NPIX);
    const float4* e2p = (const float4*)(ep + 2 * NPIX);
    const float4* e3p = (const float4*)(ep + 3 * NPIX);
    unsigned* glab = g_lab + (size_t)b * NGMAX;

    // ---------------- pass 1: kernel sums + label cache for pass 2 ------------
    // ALL loads unconditional + front-batched: 7 independent LDG.128 in flight
    // before any dependent work (MLP_p1 = 7). Masks single-use -> __ldcs.
    for (int g = gBeg + tid; g < gEnd; g += THR) {
        int4   lb = __ldcs(ip + g);
        float4 kv = __ldcs(kp + g);
        float4 mv = __ldcs(mp + g);
        float4 e0 = e0p[g];
        float4 e1 = e1p[g];
        float4 e2 = e2p[g];
        float4 e3 = e3p[g];
        int lm0 = (mv.x > 0.5f) ? lb.x : 0;
        int lm1 = (mv.y > 0.5f) ? lb.y : 0;
        int lm2 = (mv.z > 0.5f) ? lb.z : 0;
        int lm3 = (mv.w > 0.5f) ? lb.w : 0;
        glab[g] = (unsigned)lm0 | ((unsigned)lm1 << 8) | ((unsigned)lm2 << 16) | ((unsigned)lm3 << 24);
        int l0 = (kv.x > 0.5f) ? lm0 : 0;
        int l1 = (kv.y > 0.5f) ? lm1 : 0;
        int l2 = (kv.z > 0.5f) ? lm2 : 0;
        int l3 = (kv.w > 0.5f) ? lm3 : 0;
        if (l0) { atomicAdd(&sA[l0], pack3(e0.x, e1.x, e2.x)); atomicAdd(&sB[l0], packB(e3.x)); }
        if (l1) { atomicAdd(&sA[l1], pack3(e0.y, e1.y, e2.y)); atomicAdd(&sB[l1], packB(e3.y)); }
        if (l2) { atomicAdd(&sA[l2], pack3(e0.z, e1.z, e2.z)); atomicAdd(&sB[l2], packB(e3.z)); }
        if (l3) { atomicAdd(&sA[l3], pack3(e0.w, e1.w, e2.w)); atomicAdd(&sB[l3], packB(e3.w)); }
    }
    int rem = NPIX & 3;
    if (rem && chunk == 0 && tid < rem) {
        int i = NG * 4 + tid;
        const int*   ips = inst + (size_t)b * NPIX;
        const float* kps = ker  + (size_t)b * NPIX;
        const float* mps = tmk  + (size_t)b * NPIX;
        int l = (fminf(kps[i], mps[i]) > 0.5f) ? ips[i] : 0;
        if (l) {
            atomicAdd(&sA[l], pack3(ep[i], ep[i + NPIX], ep[i + 2 * NPIX]));
            atomicAdd(&sB[l], packB(ep[i + 3 * NPIX]));
        }
    }
    __syncthreads();
    if (tid >= 1 && tid < LBL) {
        int a0, a1, a2, a3, cnt, dummy;
        unpack3(sA[tid], a0, a1, a2);
        unpack3(sB[tid], a3, cnt, dummy);
        if (cnt) {
            atomicAdd(&g_s01[b * LBL + tid], (ull)(((ll)a1 << 39) + ((ll)a0 << 7)));
            atomicAdd(&g_s23[b * LBL + tid], (ull)(((ll)a3 << 39) + ((ll)a2 << 7)));
            atomicAdd(&g_cnt1[b * LBL + tid], cnt);
        }
    }
    __threadfence();
    __syncthreads();

    // ---------------- device-wide barrier (888 blocks, 6/SM — proven resident)
    if (tid == 0) {
        atomicAdd(&g_bar1, 1u);
        volatile unsigned* vb = &g_bar1;
        while (*vb < (unsigned)gridDim.x) __nanosleep(100);
    }
    __syncthreads();
    __threadfence();

    // ---------------- pass 2: distances to per-label means --------------------
    if (tid < LBL) {
        float m0 = 0.f, m1 = 0.f, m2 = 0.f, m3 = 0.f;
        if (tid > 0) {
            float inv = 1.f / fmaxf((float)g_cnt1[b * LBL + tid], 1.f);
            float a0, a1, a2, a3;
            unpack2_32(g_s01[b * LBL + tid], a0, a1);
            unpack2_32(g_s23[b * LBL + tid], a2, a3);
            m0 = a0 * inv; m1 = a1 * inv; m2 = a2 * inv; m3 = a3 * inv;
        }
        meanv[tid] = make_float4(m0, m1, m2, m3);
    }
    __syncthreads();

    // REVERSE traversal (LRU-friendly) + unconditional front-batched loads
    const int nIter = (gEnd - gBeg + THR - 1) / THR;
    for (int it = nIter - 1; it >= 0; --it) {
        const int g = gBeg + it * THR + tid;
        if (g >= gEnd) continue;
        unsigned lm = glab[g];
        float4 e0 = e0p[g];
        float4 e1 = e1p[g];
        float4 e2 = e2p[g];
        float4 e3 = e3p[g];
        if (lm != 0u) {
            #define PAN_PIX(SH, X)                                             \
                {                                                              \
                    int L = (int)((lm >> SH) & 255u);                          \
                    if (L) {                                                   \
                        float4 m = meanv[L];                                   \
                        float d0 = e0.X - m.x, d1 = e1.X - m.y;                \
                        float d2 = e2.X - m.z, d3 = e3.X - m.w;                \
                        float sq = fmaf(d0,d0, fmaf(d1,d1, fmaf(d2,d2, d3*d3)));\
                        float dist = (sq > 0.f) ? sq * rsqrtf(sq) : 0.f;       \
                        float r = fmaxf(dist - 0.5f, 0.f);                     \
                        float val = __logf(fmaf(r, r, 1.f));                   \
                        unsigned vf = (unsigned)__float2int_rn(val * S_VAL);   \
                        atomicAdd(&sp2[L], ((ull)vf << 22) + 1ull);            \
                    }                                                          \
                }
            PAN_PIX(0, x) PAN_PIX(8, y) PAN_PIX(16, z) PAN_PIX(24, w)
            #undef PAN_PIX
        }
    }
    if (rem && chunk == 0 && tid < rem) {
        int i = NG * 4 + tid;
        const int*   ips = inst + (size_t)b * NPIX;
        const float* mps = tmk  + (size_t)b * NPIX;
        int l = (mps[i] > 0.5f) ? ips[i] : 0;
        if (l) {
            float4 m = meanv[l];
            float d0 = ep[i] - m.x, d1 = ep[i+NPIX] - m.y;
            float d2 = ep[i+2*NPIX] - m.z, d3 = ep[i+3*NPIX] - m.w;
            float sq = fmaf(d0,d0, fmaf(d1,d1, fmaf(d2,d2, d3*d3)));
            float dist = (sq > 0.f) ? sq * rsqrtf(sq) : 0.f;
            float r = fmaxf(dist - 0.5f, 0.f);
            unsigned vf = (unsigned)__float2int_rn(__logf(fmaf(r, r, 1.f)) * S_VAL);
            atomicAdd(&sp2[l], ((ull)vf << 22) + 1ull);
        }
    }
    __syncthreads();
    if (tid >= 1 && tid < LBL && sp2[tid]) atomicAdd(&g_p2[b * LBL + tid], sp2[tid]);
    __threadfence();
    __syncthreads();
    if (tid == 0)
        isLast = (atomicAdd(&g_bar2, 1u) == (unsigned)gridDim.x - 1u);
    __syncthreads();
    if (!isLast) return;

    // ---------------- finalize (last block): warp w handles batch w ------------
    __threadfence();
    __shared__ float fm[BMAX][LBL][4];
    const int w = tid >> 5;
    const int l = tid & 31;

    if (w < B) {
        int   ci = g_cnt1[w * LBL + l];
        float c  = (float)ci;
        float m0 = 0.f, m1 = 0.f, m2 = 0.f, m3 = 0.f;
        if (l > 0 && ci > 0) {
            float inv = 1.f / c;
            float a0, a1, a2, a3;
            unpack2_32(g_s01[w * LBL + l], a0, a1);
            unpack2_32(g_s23[w * LBL + l], a2, a3);
            m0 = a0 * inv; m1 = a1 * inv; m2 = a2 * inv; m3 = a3 * inv;
        }
        float csum = (l > 0) ? c : 0.f;
        for (int o = 16; o; o >>= 1) csum += __shfl_xor_sync(0xffffffffu, csum, o);
        if (l == 0) c = (float)NPIX - csum;

        bool present = (c > 0.f);
        unsigned pb = __ballot_sync(0xffffffffu, present);
        int ni = __popc(pb);
        unsigned nzb = pb & ~1u;
        bool nz = present && (l > 0);

        fm[w][l][0] = m0; fm[w][l][1] = m1; fm[w][l][2] = m2; fm[w][l][3] = m3;
        __syncwarp();

        ull p2 = g_p2[w * LBL + l];
        float sv = (float)(double)(p2 >> 22) * INV_S_VAL;
        float ct = (float)(unsigned)(p2 & 0x3FFFFFull);
        float aggl = nz ? sv / fmaxf(ct, 1.f) : 0.f;

        float sq = m0*m0 + m1*m1 + m2*m2 + m3*m3;
        float nrm = (sq > 0.f) ? sqrtf(sq) : 0.f;
        float reg = present ? log1pf(nrm) : 0.f;

        float ds = 0.f, dc = 0.f;
        if (nz) {
            #pragma unroll
            for (int j = 1; j < LBL; j++) {
                if (j != l && ((nzb >> j) & 1u)) {
                    float p0 = m0 - fm[w][j][0];
                    float p1 = m1 - fm[w][j][1];
                    float p2f = m2 - fm[w][j][2];
                    float p3 = m3 - fm[w][j][3];
                    float psq = p0*p0 + p1*p1 + p2f*p2f + p3*p3;
                    float pd = (psq > 0.f) ? sqrtf(psq) : 0.f;
                    float r = fmaxf(3.0f - pd, 0.f);
                    ds += log1pf(r * r);
                    dc += 1.f;
                }
            }
        }
        for (int o = 16; o; o >>= 1) {
            aggl += __shfl_down_sync(0xffffffffu, aggl, o);
            reg  += __shfl_down_sync(0xffffffffu, reg,  o);
            ds   += __shfl_down_sync(0xffffffffu, ds,   o);
            dc   += __shfl_down_sync(0xffffffffu, dc,   o);
        }
        if (l == 0) {
            float l_agg = aggl / (float)((ni - 1) > 1 ? (ni - 1) : 1);
            float l_reg = reg / (float)(ni > 1 ? ni : 1) * 0.001f;
            float l_dis = (ni > 2) ? ds / fmaxf(dc, 1.f) : 0.f;
            out[w] = (ni <= 1) ? 0.f : (l_agg + l_dis + l_reg);
        }
    }
    __syncthreads();
    if (tid < BMAX * LBL) {
        g_s01[tid] = 0ull;
        g_s23[tid] = 0ull;
        g_cnt1[tid] = 0;
        g_p2[tid]  = 0ull;
    }
    if (tid == 0) { g_bar1 = 0u; g_bar2 = 0u; }
}

extern "C" void kernel_launch(void* const* d_in, const int* in_sizes, int n_in,
                              void* d_out, int out_size) {
    const float* emb  = (const float*)d_in[0];
    const int*   inst = (const int*)  d_in[1];
    const float* ker  = (const float*)d_in[2];
    const float* tmk  = (const float*)d_in[3];
    float* out = (float*)d_out;

    int B = out_size;
    if (B > BMAX) B = BMAX;
    int NPIX = in_sizes[1] / B;
    int NG = NPIX >> 2;
    if (NG > NGMAX) NG = NGMAX;   // fixed problem shape: 135424

    // 888 blocks = 148 SMs x 6 — the residency envelope proven in R5-R7
    k_fused<<<B * NCHUNK, THR>>>(emb, inst, ker, tmk, out, NG, NPIX, B);
}